// round 16
// baseline (speedup 1.0000x reference)
#include <cuda_runtime.h>
#include <cuda_fp16.h>
#include <math.h>

#define N_NODES 50000
#define N_EDGES 800000
#define FEAT    128
#define SCAN_BLOCKS 196   // ceil(50000/256)

// Scratch (device globals; no allocation allowed in kernel_launch).
__device__ float g_w[N_NODES];                        // w = exp(x @ a)
__device__ int   g_cnt[N_NODES];                      // degree (re-zeroed by scanA)
__device__ int   g_rowptr[N_NODES + 1];               // CSR row pointers
__device__ int   g_blocksum[SCAN_BLOCKS];             // scan partials
__device__ __align__(16) int g_rank[N_EDGES];         // edge rank within its row
__device__ __align__(16) int g_cidx[N_EDGES];         // CSR column indices
__device__ __align__(16) __half g_xh[N_NODES * FEAT]; // fp16 copy of x (uint2 per lane)

// K1: fused — w[i] = exp(dot(x[i,:], a)) (warp per node), fp16 copy of x,
// degree histogram + per-edge rank capture (thread per edge).
__global__ void k_score(const float* __restrict__ x, const float* __restrict__ a,
                        const int* __restrict__ row) {
    __shared__ float sa[FEAT];
    int tid = threadIdx.x;
    if (tid < FEAT) sa[tid] = a[tid];
    __syncthreads();
    int gt = blockIdx.x * blockDim.x + tid;

    // histogram + rank (the atomic's return value IS the rank)
    if (gt < N_EDGES) g_rank[gt] = atomicAdd(&g_cnt[row[gt]], 1);

    int gwarp = gt >> 5;
    int lane = tid & 31;
    if (gwarp >= N_NODES) return;
    float4 v = ((const float4*)x)[gwarp * 32 + lane];

    __half2 p0 = __floats2half2_rn(v.x, v.y);
    __half2 p1 = __floats2half2_rn(v.z, v.w);
    uint2 packed;
    packed.x = *(unsigned int*)&p0;
    packed.y = *(unsigned int*)&p1;
    ((uint2*)g_xh)[gwarp * 32 + lane] = packed;

    float4 w = ((const float4*)sa)[lane];
    float s = v.x * w.x + v.y * w.y + v.z * w.z + v.w * w.w;
    #pragma unroll
    for (int o = 16; o; o >>= 1) s += __shfl_xor_sync(0xffffffffu, s, o);
    if (lane == 0) g_w[gwarp] = expf(s);   // e ~ N(0, sqrt(2)) -> exp safe in fp32
}

// K2a: per-block exclusive scan of g_cnt -> g_rowptr (local), totals -> g_blocksum.
// Re-zeroes g_cnt for the next graph replay.
__global__ void k_scanA() {
    int i = blockIdx.x * 256 + threadIdx.x;
    int v = 0;
    if (i < N_NODES) { v = g_cnt[i]; g_cnt[i] = 0; }
    int lane = threadIdx.x & 31, w = threadIdx.x >> 5;
    int s = v;
    #pragma unroll
    for (int o = 1; o < 32; o <<= 1) {
        int t = __shfl_up_sync(0xffffffffu, s, o);
        if (lane >= o) s += t;
    }
    __shared__ int ws[8];
    if (lane == 31) ws[w] = s;
    __syncthreads();
    if (w == 0) {
        int t = (lane < 8) ? ws[lane] : 0;
        #pragma unroll
        for (int o = 1; o < 8; o <<= 1) {
            int u = __shfl_up_sync(0xffffffffu, t, o);
            if (lane >= o) t += u;
        }
        if (lane < 8) ws[lane] = t;
    }
    __syncthreads();
    int excl = s - v + (w > 0 ? ws[w - 1] : 0);
    if (i < N_NODES) g_rowptr[i] = excl;
    if (threadIdx.x == 0) g_blocksum[blockIdx.x] = ws[7];
}

// K2b: each block computes its prefix over g_blocksum by block-reduce,
// adds it to its rowptr slice.
__global__ void k_scanB() {
    int tid = threadIdx.x;
    int v = (tid < SCAN_BLOCKS && tid < blockIdx.x) ? g_blocksum[tid] : 0;
    int lane = tid & 31, w = tid >> 5;
    #pragma unroll
    for (int o = 16; o; o >>= 1) v += __shfl_xor_sync(0xffffffffu, v, o);
    __shared__ int ws[8];
    if (lane == 0) ws[w] = v;
    __syncthreads();
    if (tid == 0) {
        int t = 0;
        #pragma unroll
        for (int j = 0; j < 8; j++) t += ws[j];
        ws[0] = t;
    }
    __syncthreads();
    int prefix = ws[0];

    int i = blockIdx.x * 256 + tid;
    if (i < N_NODES) g_rowptr[i] += prefix;
    if (i == 0) g_rowptr[N_NODES] = N_EDGES;
}

// K3: counting-sort fill — NO atomics, NO w gather. Per edge: one rowptr
// gather + one 4B cidx scatter (2 divergent accesses). 2 edges/thread.
__global__ void k_fill(const int* __restrict__ row, const int* __restrict__ col) {
    int t = blockIdx.x * blockDim.x + threadIdx.x;   // N_EDGES/2 threads
    if (t >= N_EDGES / 2) return;
    int2 r2 = ((const int2*)row)[t];
    int2 c2 = ((const int2*)col)[t];
    int2 k2 = ((const int2*)g_rank)[t];

    int p0 = g_rowptr[r2.x] + k2.x;
    int p1 = g_rowptr[r2.y] + k2.y;

    g_cidx[p0] = c2.x;
    g_cidx[p1] = c2.y;
}

// K4: warp per row. Chunked: warp cooperatively loads up to 32 edges'
// cidx (coalesced) + w (gather) in TWO LDGs, then per edge SHFL-broadcasts
// c and w and issues ONE LDG.64 per lane (256B fp16 row). wsum accumulates
// from the per-lane w vector, reduced once at the end.
__global__ void k_row(float* __restrict__ h) {
    int gw = (blockIdx.x * blockDim.x + threadIdx.x) >> 5;
    int lane = threadIdx.x & 31;
    if (gw >= N_NODES) return;
    int s0 = g_rowptr[gw], s1 = g_rowptr[gw + 1];

    const uint2* xh = (const uint2*)g_xh;   // 8B = 4 halves per lane
    float4 acc = make_float4(0.f, 0.f, 0.f, 0.f);
    float wsum = 0.0f;

    for (int chunk = s0; chunk < s1; chunk += 32) {
        int n = s1 - chunk; if (n > 32) n = 32;
        int   ci = 0;
        float wi = 0.0f;
        if (lane < n) {
            ci = __ldg(&g_cidx[chunk + lane]);   // one coalesced LDG / 32 edges
            wi = __ldg(&g_w[ci]);                // one gather LDG / 32 edges
        }
        wsum += wi;
        for (int j = 0; j < n; j++) {
            int   c   = __shfl_sync(0xffffffffu, ci, j);
            float wgt = __shfl_sync(0xffffffffu, wi, j);
            uint2 p = xh[c * 32 + lane];         // one LDG.64 per lane per edge
            float2 f0 = __half22float2(*(__half2*)&p.x);
            float2 f1 = __half22float2(*(__half2*)&p.y);
            acc.x += wgt * f0.x;
            acc.y += wgt * f0.y;
            acc.z += wgt * f1.x;
            acc.w += wgt * f1.y;
        }
    }

    // reduce wsum across the warp
    #pragma unroll
    for (int o = 16; o; o >>= 1) wsum += __shfl_xor_sync(0xffffffffu, wsum, o);

    float inv = (s1 > s0) ? 1.0f / wsum : 0.0f;
    acc.x *= inv; acc.y *= inv; acc.z *= inv; acc.w *= inv;
    ((float4*)h)[gw * 32 + lane] = acc;
}

extern "C" void kernel_launch(void* const* d_in, const int* in_sizes, int n_in,
                              void* d_out, int out_size) {
    const float* x   = (const float*)d_in[0];  // [N_NODES, FEAT]
    const float* a   = (const float*)d_in[1];  // [FEAT, 1]
    const int*   row = (const int*)d_in[2];    // [N_EDGES] int32
    const int*   col = (const int*)d_in[3];    // [N_EDGES] int32
    float* h = (float*)d_out;                  // [N_NODES, FEAT]

    int score_blocks = (N_NODES * 32 + 255) / 256;   // warp/node + thread/edge
    k_score<<<score_blocks, 256>>>(x, a, row);

    k_scanA<<<SCAN_BLOCKS, 256>>>();
    k_scanB<<<SCAN_BLOCKS, 256>>>();

    int fill_blocks = (N_EDGES / 2 + 255) / 256;     // 2 edges per thread
    k_fill<<<fill_blocks, 256>>>(row, col);

    int row_blocks = (N_NODES * 32 + 255) / 256;     // warp per row
    k_row<<<row_blocks, 256>>>(h);
}

// round 17
// speedup vs baseline: 1.0775x; 1.0775x over previous
#include <cuda_runtime.h>
#include <cuda_fp16.h>
#include <math.h>

#define N_NODES 50000
#define N_EDGES 800000
#define FEAT    128
#define SCAN_BLOCKS 196   // ceil(50000/256)

// Scratch (device globals; no allocation allowed in kernel_launch).
__device__ float g_w[N_NODES];                        // w = exp(x @ a)
__device__ int   g_cnt[N_NODES];                      // degree (re-zeroed by k_scan)
__device__ int   g_rowptr[N_NODES + 1];               // CSR row pointers
__device__ volatile int g_blocksum[SCAN_BLOCKS];      // published block totals
__device__ volatile int g_flag[SCAN_BLOCKS];          // publish flags (reset by k_score)
__device__ __align__(16) int g_rank[N_EDGES];         // edge rank within its row
__device__ __align__(16) int g_cidx[N_EDGES];         // CSR column indices
__device__ __align__(16) __half g_xh[N_NODES * FEAT]; // fp16 copy of x (uint4/16 lanes)

// K1: fused — w[i] = exp(dot(x[i,:], a)) (warp per node), fp16 copy of x,
// degree histogram + per-edge rank capture (thread per edge), scan-flag reset.
__global__ void k_score(const float* __restrict__ x, const float* __restrict__ a,
                        const int* __restrict__ row) {
    __shared__ float sa[FEAT];
    int tid = threadIdx.x;
    if (tid < FEAT) sa[tid] = a[tid];
    __syncthreads();
    int gt = blockIdx.x * blockDim.x + tid;

    if (gt < SCAN_BLOCKS) g_flag[gt] = 0;   // reset single-pass scan flags

    // histogram + rank (the atomic's return value IS the rank)
    if (gt < N_EDGES) g_rank[gt] = atomicAdd(&g_cnt[row[gt]], 1);

    int gwarp = gt >> 5;
    int lane = tid & 31;
    if (gwarp >= N_NODES) return;
    float4 v = ((const float4*)x)[gwarp * 32 + lane];

    __half2 p0 = __floats2half2_rn(v.x, v.y);
    __half2 p1 = __floats2half2_rn(v.z, v.w);
    uint2 packed;
    packed.x = *(unsigned int*)&p0;
    packed.y = *(unsigned int*)&p1;
    ((uint2*)g_xh)[gwarp * 32 + lane] = packed;

    float4 w = ((const float4*)sa)[lane];
    float s = v.x * w.x + v.y * w.y + v.z * w.z + v.w * w.w;
    #pragma unroll
    for (int o = 16; o; o >>= 1) s += __shfl_xor_sync(0xffffffffu, s, o);
    if (lane == 0) g_w[gwarp] = expf(s);   // e ~ N(0, sqrt(2)) -> exp safe in fp32
}

// K2: SINGLE-PASS exclusive scan of g_cnt -> g_rowptr. Each block scans its
// 256 counts locally, publishes its total (fence + flag), then polls all
// predecessor totals (one per thread) and adds the prefix. All 196 blocks
// are co-resident; publish-before-poll makes this deadlock-free regardless.
// Also re-zeroes g_cnt for the next graph replay.
__global__ void k_scan() {
    int b = blockIdx.x;
    int i = b * 256 + threadIdx.x;
    int v = 0;
    if (i < N_NODES) { v = g_cnt[i]; g_cnt[i] = 0; }
    int lane = threadIdx.x & 31, w = threadIdx.x >> 5;
    int s = v;
    #pragma unroll
    for (int o = 1; o < 32; o <<= 1) {
        int t = __shfl_up_sync(0xffffffffu, s, o);
        if (lane >= o) s += t;
    }
    __shared__ int ws[8];
    if (lane == 31) ws[w] = s;
    __syncthreads();
    if (w == 0) {
        int t = (lane < 8) ? ws[lane] : 0;
        #pragma unroll
        for (int o = 1; o < 8; o <<= 1) {
            int u = __shfl_up_sync(0xffffffffu, t, o);
            if (lane >= o) t += u;
        }
        if (lane < 8) ws[lane] = t;
    }
    __syncthreads();
    int excl = s - v + (w > 0 ? ws[w - 1] : 0);   // block-local exclusive

    // publish this block's total
    if (threadIdx.x == 0) {
        g_blocksum[b] = ws[7];
        __threadfence();
        g_flag[b] = 1;
    }

    // poll predecessors: thread t waits for block t (t < b), reads its total
    int mysum = 0;
    if (threadIdx.x < b) {
        while (g_flag[threadIdx.x] == 0) {}
        mysum = g_blocksum[threadIdx.x];
    }
    // block-reduce mysum -> prefix
    #pragma unroll
    for (int o = 16; o; o >>= 1) mysum += __shfl_xor_sync(0xffffffffu, mysum, o);
    __shared__ int rs[8];
    __syncthreads();               // ws reuse barrier not needed; rs separate
    if (lane == 0) rs[w] = mysum;
    __syncthreads();
    if (threadIdx.x == 0) {
        int t = 0;
        #pragma unroll
        for (int j = 0; j < 8; j++) t += rs[j];
        rs[0] = t;
    }
    __syncthreads();
    int prefix = rs[0];

    if (i < N_NODES) g_rowptr[i] = excl + prefix;
    if (i == N_NODES) g_rowptr[N_NODES] = N_EDGES;
    if (b == SCAN_BLOCKS - 1 && threadIdx.x == 255) g_rowptr[N_NODES] = N_EDGES;
}

// K3: counting-sort fill — NO atomics, NO w gather. Per edge: one rowptr
// gather + one 4B cidx scatter (2 divergent accesses). 2 edges/thread.
__global__ void k_fill(const int* __restrict__ row, const int* __restrict__ col) {
    int t = blockIdx.x * blockDim.x + threadIdx.x;   // N_EDGES/2 threads
    if (t >= N_EDGES / 2) return;
    int2 r2 = ((const int2*)row)[t];
    int2 c2 = ((const int2*)col)[t];
    int2 k2 = ((const int2*)g_rank)[t];

    int p0 = g_rowptr[r2.x] + k2.x;
    int p1 = g_rowptr[r2.y] + k2.y;

    g_cidx[p0] = c2.x;
    g_cidx[p1] = c2.y;
}

// K4: warp per row, HALF-WARP per edge. Feature stream loaded with
// L1::no_allocate so the 12.8MB gather doesn't thrash L1 — keeps g_w
// (200KB) and cidx lines L1-resident for the per-edge broadcast loads.
__global__ void k_row(float* __restrict__ h) {
    int gw = (blockIdx.x * blockDim.x + threadIdx.x) >> 5;
    int lane = threadIdx.x & 31;
    if (gw >= N_NODES) return;
    int s0 = g_rowptr[gw], s1 = g_rowptr[gw + 1];

    int half = lane >> 4;        // 0 or 1
    int hl   = lane & 15;        // lane within half-warp

    float acc[8] = {0.f, 0.f, 0.f, 0.f, 0.f, 0.f, 0.f, 0.f};
    float wsum = 0.0f;

    for (int i = s0 + half; i < s1; i += 2) {
        int c = __ldg(&g_cidx[i]);           // broadcast, L1-resident
        float wgt = __ldg(&g_w[c]);          // broadcast gather, L1-resident
        wsum += wgt;
        const __half* fp = g_xh + (size_t)c * FEAT + hl * 8;
        uint4 p;
        asm("ld.global.nc.L1::no_allocate.v4.b32 {%0,%1,%2,%3}, [%4];"
            : "=r"(p.x), "=r"(p.y), "=r"(p.z), "=r"(p.w) : "l"(fp));
        float2 f0 = __half22float2(*(__half2*)&p.x);
        float2 f1 = __half22float2(*(__half2*)&p.y);
        float2 f2 = __half22float2(*(__half2*)&p.z);
        float2 f3 = __half22float2(*(__half2*)&p.w);
        acc[0] += wgt * f0.x;  acc[1] += wgt * f0.y;
        acc[2] += wgt * f1.x;  acc[3] += wgt * f1.y;
        acc[4] += wgt * f2.x;  acc[5] += wgt * f2.y;
        acc[6] += wgt * f3.x;  acc[7] += wgt * f3.y;
    }

    // combine the two half-warps (lane i += lane i+16)
    #pragma unroll
    for (int j = 0; j < 8; j++)
        acc[j] += __shfl_down_sync(0xffffffffu, acc[j], 16);
    wsum += __shfl_down_sync(0xffffffffu, wsum, 16);

    if (half == 0) {
        float inv = (s1 > s0) ? 1.0f / wsum : 0.0f;
        float4 o0 = make_float4(acc[0] * inv, acc[1] * inv, acc[2] * inv, acc[3] * inv);
        float4 o1 = make_float4(acc[4] * inv, acc[5] * inv, acc[6] * inv, acc[7] * inv);
        float4* dst = (float4*)(h + (size_t)gw * FEAT + hl * 8);
        dst[0] = o0;
        dst[1] = o1;
    }
}

extern "C" void kernel_launch(void* const* d_in, const int* in_sizes, int n_in,
                              void* d_out, int out_size) {
    const float* x   = (const float*)d_in[0];  // [N_NODES, FEAT]
    const float* a   = (const float*)d_in[1];  // [FEAT, 1]
    const int*   row = (const int*)d_in[2];    // [N_EDGES] int32
    const int*   col = (const int*)d_in[3];    // [N_EDGES] int32
    float* h = (float*)d_out;                  // [N_NODES, FEAT]

    int score_blocks = (N_NODES * 32 + 255) / 256;   // warp/node + thread/edge
    k_score<<<score_blocks, 256>>>(x, a, row);

    k_scan<<<SCAN_BLOCKS, 256>>>();                  // single-pass scan

    int fill_blocks = (N_EDGES / 2 + 255) / 256;     // 2 edges per thread
    k_fill<<<fill_blocks, 256>>>(row, col);

    int row_blocks = (N_NODES * 32 + 255) / 256;     // warp per row
    k_row<<<row_blocks, 256>>>(h);
}